// round 14
// baseline (speedup 1.0000x reference)
#include <cuda_runtime.h>

// AdderVDSR collapses analytically (verified R1-R7, rel_err ~1.2e-7):
//   adder_conv = -sum|..| < 0, no bias => relu -> exact 0, propagates through all
//   16 layers => out = out_b + pixel_shuffle(conv3(x, up_w, up_b), 2).
// R11: R7 register-x core, launch geometry change: grid 128 x block 512
//      (2 rows per CTA) to halve CTA dispatch + cross-CTA L1tex spread.

#define Bn  2
#define CIN 3
#define Hn  128
#define Wn  128
#define OC  12

__device__ __forceinline__ unsigned long long pack2(float lo, float hi) {
    unsigned long long r;
    asm("mov.b64 %0, {%1, %2};" : "=l"(r) : "f"(lo), "f"(hi));
    return r;
}
__device__ __forceinline__ void unpack2(unsigned long long v, float& lo, float& hi) {
    asm("mov.b64 {%0, %1}, %2;" : "=f"(lo), "=f"(hi) : "l"(v));
}
__device__ __forceinline__ unsigned long long fma2(unsigned long long a,
                                                   unsigned long long b,
                                                   unsigned long long c) {
    unsigned long long d;
    asm("fma.rn.f32x2 %0, %1, %2, %3;" : "=l"(d) : "l"(a), "l"(b), "l"(c));
    return d;
}

__global__ __launch_bounds__(512) void adder_vdsr_r11_kernel(
    const float* __restrict__ x,      // [2, 3, 128, 128]
    const float* __restrict__ up_w,   // [12, 3, 3, 3]
    const float* __restrict__ up_b,   // [12]
    const float* __restrict__ out_b,  // [3]
    float* __restrict__ out)          // [2, 3, 256, 256]
{
    __shared__ __align__(16) float ws[27 * OC];   // transposed: ws[k*12 + o]

    int t  = threadIdx.x;                         // 0..511
    int sr = t >> 8;                              // sub-row 0/1
    int g  = (t >> 7) & 1;                        // channel group 0/1
    int w  = t & (Wn - 1);                        // w position 0..127
    int bh = (blockIdx.x << 1) + sr;              // over B*H = 256
    int h  = bh & (Hn - 1);
    int b  = bh >> 7;

    // ---- 27 front-batched x loads straight into registers ----
    const float* xb = x + b * (CIN * Hn * Wn);
    float x27[27];
#pragma unroll
    for (int ic = 0; ic < CIN; ic++) {
        const float* xc = xb + ic * (Hn * Wn);
#pragma unroll
        for (int dy = 0; dy < 3; dy++) {
            int yy = h + dy - 1;
            bool yok = ((unsigned)yy < (unsigned)Hn);
            const float* xr = xc + yy * Wn + (w - 1);
#pragma unroll
            for (int dx = 0; dx < 3; dx++) {
                int xx = w + dx - 1;
                bool ok = yok && ((unsigned)xx < (unsigned)Wn);
                x27[(ic * 3 + dy) * 3 + dx] = ok ? __ldg(xr + dx) : 0.0f;
            }
        }
    }

    // ---- bias pairs direct from gmem (no smem, no barrier dependency) ----
    // pair p = 3g+jj covers channels {2p, 2p+1}; out_b channel = (2p)>>2 = p>>1
    unsigned long long acc2[3];
#pragma unroll
    for (int jj = 0; jj < 3; jj++) {
        int p = 3 * g + jj;
        float bias_lo = __ldg(up_b + 2 * p)     + __ldg(out_b + (p >> 1));
        float bias_hi = __ldg(up_b + 2 * p + 1) + __ldg(out_b + (p >> 1));
        acc2[jj] = pack2(bias_lo, bias_hi);
    }

    // ---- weights transposed into smem (overlaps x/bias LDGs above) ----
    for (int i = t; i < 27 * OC; i += 512) {
        int o  = i / 27;
        int kk = i - o * 27;
        ws[kk * OC + o] = up_w[i];
    }
    __syncthreads();                              // gates ONLY weight consumption

    // ---- packed f32x2 accumulation: this group's 3 channel-pairs ----
    const unsigned long long* ws2 = reinterpret_cast<const unsigned long long*>(ws);
#pragma unroll
    for (int kk = 0; kk < 27; kk++) {
        unsigned long long vv = pack2(x27[kk], x27[kk]);
#pragma unroll
        for (int jj = 0; jj < 3; jj++)
            acc2[jj] = fma2(vv, ws2[kk * 6 + 3 * g + jj], acc2[jj]);
    }

    // ---- pixel-shuffle store: pair p=3g+jj -> (c=p>>1, i=p&1); bias pre-folded ----
    float* ob = out + b * (CIN * 2 * Hn * 2 * Wn);
#pragma unroll
    for (int jj = 0; jj < 3; jj++) {
        int p = 3 * g + jj;
        int c = p >> 1;
        int i = p & 1;
        float lo, hi;
        unpack2(acc2[jj], lo, hi);
        *reinterpret_cast<float2*>(ob + (c * 2 * Hn + 2 * h + i) * (2 * Wn) + 2 * w)
            = make_float2(lo, hi);
    }
}

extern "C" void kernel_launch(void* const* d_in, const int* in_sizes, int n_in,
                              void* d_out, int out_size)
{
    // metadata order: x, up_w, up_b, in_w, in_b, adder_w, out_w, out_b
    const float* x     = (const float*)d_in[0];
    const float* up_w  = (const float*)d_in[1];
    const float* up_b  = (const float*)d_in[2];
    const float* out_b = (const float*)d_in[7];
    float* out = (float*)d_out;

    adder_vdsr_r11_kernel<<<(Bn * Hn) / 2, 512>>>(x, up_w, up_b, out_b, out);
}

// round 15
// speedup vs baseline: 1.3077x; 1.3077x over previous
#include <cuda_runtime.h>

// AdderVDSR collapses analytically (verified R1-R11, rel_err ~1.2e-7):
//   adder_conv = -sum|..| < 0, no bias => relu -> exact 0, propagates through all
//   16 layers => out = out_b + pixel_shuffle(conv3(x, up_w, up_b), 2).
// R14: R7 core (best measured kernel, grid 256 x 256) + direct-LDG bias
//      (barrier gates only the weight smem). Clock-ramp-bound regime:
//      minimize single-CTA critical path.

#define Bn  2
#define CIN 3
#define Hn  128
#define Wn  128
#define OC  12

__device__ __forceinline__ unsigned long long pack2(float lo, float hi) {
    unsigned long long r;
    asm("mov.b64 %0, {%1, %2};" : "=l"(r) : "f"(lo), "f"(hi));
    return r;
}
__device__ __forceinline__ void unpack2(unsigned long long v, float& lo, float& hi) {
    asm("mov.b64 {%0, %1}, %2;" : "=f"(lo), "=f"(hi) : "l"(v));
}
__device__ __forceinline__ unsigned long long fma2(unsigned long long a,
                                                   unsigned long long b,
                                                   unsigned long long c) {
    unsigned long long d;
    asm("fma.rn.f32x2 %0, %1, %2, %3;" : "=l"(d) : "l"(a), "l"(b), "l"(c));
    return d;
}

__global__ __launch_bounds__(256) void adder_vdsr_r14_kernel(
    const float* __restrict__ x,      // [2, 3, 128, 128]
    const float* __restrict__ up_w,   // [12, 3, 3, 3]
    const float* __restrict__ up_b,   // [12]
    const float* __restrict__ out_b,  // [3]
    float* __restrict__ out)          // [2, 3, 256, 256]
{
    __shared__ __align__(16) float ws[27 * OC];   // transposed: ws[k*12 + o]

    int t  = threadIdx.x;                         // 0..255
    int g  = t >> 7;                              // channel group 0/1
    int w  = t & (Wn - 1);                        // w position 0..127
    int bh = blockIdx.x;                          // over B*H = 256
    int h  = bh & (Hn - 1);
    int b  = bh >> 7;

    // ---- 27 front-batched x loads straight into registers (MLP=27) ----
    const float* xb = x + b * (CIN * Hn * Wn);
    float x27[27];
#pragma unroll
    for (int ic = 0; ic < CIN; ic++) {
        const float* xc = xb + ic * (Hn * Wn);
#pragma unroll
        for (int dy = 0; dy < 3; dy++) {
            int yy = h + dy - 1;
            bool yok = ((unsigned)yy < (unsigned)Hn);
            const float* xr = xc + yy * Wn + (w - 1);
#pragma unroll
            for (int dx = 0; dx < 3; dx++) {
                int xx = w + dx - 1;
                bool ok = yok && ((unsigned)xx < (unsigned)Wn);
                x27[(ic * 3 + dy) * 3 + dx] = ok ? __ldg(xr + dx) : 0.0f;
            }
        }
    }

    // ---- bias pairs direct from gmem (no smem, not barrier-gated) ----
    // pair p = 3g+jj covers channels {2p, 2p+1}; out_b channel = p>>1
    unsigned long long acc2[3];
#pragma unroll
    for (int jj = 0; jj < 3; jj++) {
        int p = 3 * g + jj;
        float ob2 = __ldg(out_b + (p >> 1));
        acc2[jj] = pack2(__ldg(up_b + 2 * p) + ob2,
                         __ldg(up_b + 2 * p + 1) + ob2);
    }

    // ---- weights transposed into smem (overlaps x/bias LDGs above) ----
    for (int i = t; i < 27 * OC; i += 256) {
        int o  = i / 27;
        int kk = i - o * 27;
        ws[kk * OC + o] = up_w[i];
    }
    __syncthreads();                              // gates ONLY weight consumption

    // ---- packed f32x2 accumulation: this group's 3 channel-pairs ----
    const unsigned long long* ws2 = reinterpret_cast<const unsigned long long*>(ws);
#pragma unroll
    for (int kk = 0; kk < 27; kk++) {
        unsigned long long vv = pack2(x27[kk], x27[kk]);
#pragma unroll
        for (int jj = 0; jj < 3; jj++)
            acc2[jj] = fma2(vv, ws2[kk * 6 + 3 * g + jj], acc2[jj]);
    }

    // ---- pixel-shuffle store: pair p=3g+jj -> (c=p>>1, i=p&1); bias pre-folded ----
    float* ob = out + b * (CIN * 2 * Hn * 2 * Wn);
#pragma unroll
    for (int jj = 0; jj < 3; jj++) {
        int p = 3 * g + jj;
        int c = p >> 1;
        int i = p & 1;
        float lo, hi;
        unpack2(acc2[jj], lo, hi);
        *reinterpret_cast<float2*>(ob + (c * 2 * Hn + 2 * h + i) * (2 * Wn) + 2 * w)
            = make_float2(lo, hi);
    }
}

extern "C" void kernel_launch(void* const* d_in, const int* in_sizes, int n_in,
                              void* d_out, int out_size)
{
    // metadata order: x, up_w, up_b, in_w, in_b, adder_w, out_w, out_b
    const float* x     = (const float*)d_in[0];
    const float* up_w  = (const float*)d_in[1];
    const float* up_b  = (const float*)d_in[2];
    const float* out_b = (const float*)d_in[7];
    float* out = (float*)d_out;

    adder_vdsr_r14_kernel<<<Bn * Hn, 256>>>(x, up_w, up_b, out_b, out);
}